// round 6
// baseline (speedup 1.0000x reference)
#include <cuda_runtime.h>
#include <cuda_bf16.h>
#include <cstdint>
#include <cstddef>

// Problem constants
#define BATCH 4
#define SEQ   2048
#define DIM   1024
#define SOFTMAX_SCALE 0.03125f  // 1/sqrt(1024)

// ---------------------------------------------------------------------------
// tcgen05 availability: only in arch-specific ('a' / family) compile passes.
// Plain compute_103 pass falls back to legacy mma.sync.
// ---------------------------------------------------------------------------
#if defined(__CUDA_ARCH__) && (__CUDA_ARCH__ >= 1000) && \
    (defined(__CUDA_ARCH_FEAT_SM103_ALL) || defined(__CUDA_ARCH_FEAT_SM100_ALL) || \
     defined(__CUDA_ARCH_FEAT_SM101_ALL) || defined(__CUDA_ARCH_FAMILY_SPECIFIC__))
#define HAS_TCGEN05 1
#else
#define HAS_TCGEN05 0
#endif

// CTA tile: 256 (M) x 256 (N) as two stacked M=128 cg1 MMAs sharing one B tile.
#define NSTAGE 3

// SMEM layout (bytes, within dynamic smem)
#define SMEM_TMEM   0
#define SMEM_EMPTY(s) (16 + 8 * (s))     // 16..39
#define SMEM_DONE   48
#define SMEM_A(s)   (1024 + (s) * 32768)                   // 256 rows x 128B
#define SMEM_B(s)   (1024 + NSTAGE * 32768 + (s) * 32768)  // 256 rows x 128B
#define SMEM_TOTAL  (1024 + 2 * NSTAGE * 32768)            // 197632

// idesc: kind::tf32, D=f32, A=B=tf32 (enc 2), K-major, M=128, N=256
#define MMA_IDESC ((1u << 4) | (2u << 7) | (2u << 10) | (32u << 17) | (8u << 24))

// ---------------------------------------------------------------------------
// Scratch (device globals; allocation in kernel_launch is forbidden)
// ---------------------------------------------------------------------------
__device__ float g_qr[BATCH * SEQ * DIM];   // query, tf32-rounded
__device__ float g_kr[BATCH * SEQ * DIM];   // key_in, tf32-rounded
__device__ float g_wq[DIM * DIM];           // Wq, tf32-rounded
__device__ float g_wk[DIM * DIM];           // Wk, tf32-rounded
__device__ float g_vt[BATCH * SEQ * DIM];   // value transposed [B][D][S], rounded
__device__ float g_q [BATCH * SEQ * DIM];   // projected q
__device__ float g_k [BATCH * SEQ * DIM];   // projected k
__device__ float g_dots[(size_t)BATCH * SEQ * SEQ];

// ---------------------------------------------------------------------------
// Common helpers
// ---------------------------------------------------------------------------
__device__ __forceinline__ float tf32r(float f) {
    uint32_t u;
    asm("cvt.rna.tf32.f32 %0, %1;" : "=r"(u) : "f"(f));
    return __uint_as_float(u);
}

__device__ __forceinline__ uint32_t f2tf(float f) {
    uint32_t u;
    asm("cvt.rna.tf32.f32 %0, %1;" : "=r"(u) : "f"(f));
    return u;
}

__device__ __forceinline__ uint32_t smem_u32(const void* p) {
    uint32_t a;
    asm("{ .reg .u64 t; cvta.to.shared.u64 t, %1; cvt.u32.u64 %0, t; }" : "=r"(a) : "l"(p));
    return a;
}

#if HAS_TCGEN05
// ---------------------------------------------------------------------------
// tcgen05-only helpers (arch-specific pass) — identical to the validated R4 set
// ---------------------------------------------------------------------------
__device__ __forceinline__ uint32_t elect_one_pred() {
    uint32_t pred;
    asm volatile(
        "{\n\t.reg .pred p;\n\t"
        "elect.sync _|p, 0xFFFFFFFF;\n\t"
        "selp.b32 %0, 1, 0, p;\n\t}"
        : "=r"(pred));
    return pred;
}

#define MBARRIER_INIT(addr, cnt) \
    asm volatile("mbarrier.init.shared.b64 [%0], %1;" :: "r"((uint32_t)(addr)), "r"((uint32_t)(cnt)) : "memory")

#define MBARRIER_WAIT_PARITY(addr, parity) do {                                        \
    uint32_t _mbar = (uint32_t)(addr);                                                 \
    uint32_t _par  = (uint32_t)(parity);                                               \
    uint32_t _done;                                                                    \
    asm volatile(                                                                      \
        "{\n\t.reg .pred p;\n\t"                                                       \
        "mbarrier.try_wait.parity.acquire.cta.shared::cta.b64 p, [%1], %2;\n\t"        \
        "selp.b32 %0, 1, 0, p;\n\t}"                                                   \
        : "=r"(_done) : "r"(_mbar), "r"(_par) : "memory");                             \
    if (!_done) {                                                                      \
        asm volatile(                                                                  \
            "{\n\t.reg .pred P1;\n\t"                                                  \
            "WAIT_LOOP_%=:\n\t"                                                        \
            "mbarrier.try_wait.parity.acquire.cta.shared::cta.b64 P1, [%0], %1, 0x989680;\n\t" \
            "@P1 bra.uni WAIT_DONE_%=;\n\t"                                            \
            "bra.uni WAIT_LOOP_%=;\n\t"                                                 \
            "WAIT_DONE_%=:\n\t}"                                                        \
            :: "r"(_mbar), "r"(_par) : "memory");                                      \
    }                                                                                  \
} while (0)

#define TCGEN05_ALLOC(smem_addr, ncols) \
    asm volatile("tcgen05.alloc.cta_group::1.sync.aligned.shared::cta.b32 [%0], %1;" \
        :: "r"((uint32_t)(smem_addr)), "r"((uint32_t)(ncols)) : "memory")
#define TCGEN05_DEALLOC(tmem, ncols) \
    asm volatile("tcgen05.dealloc.cta_group::1.sync.aligned.b32 %0, %1;" :: "r"(tmem), "r"((uint32_t)(ncols)))
#define TCGEN05_RELINQUISH() \
    asm volatile("tcgen05.relinquish_alloc_permit.cta_group::1.sync.aligned;")
#define TCGEN05_COMMIT(mbar) \
    asm volatile("tcgen05.commit.cta_group::1.mbarrier::arrive::one.shared::cluster.b64 [%0];" \
        :: "r"((uint32_t)(mbar)) : "memory")
#define TCGEN05_FENCE_AFTER()  asm volatile("tcgen05.fence::after_thread_sync;"  ::: "memory")
#define TCGEN05_FENCE_BEFORE() asm volatile("tcgen05.fence::before_thread_sync;" ::: "memory")
#define TCGEN05_WAIT_LD()      asm volatile("tcgen05.wait::ld.sync.aligned;"     ::: "memory")

#define CP_ASYNC16(sm, g) \
    asm volatile("cp.async.cg.shared.global [%0], [%1], 16;" :: "r"(sm), "l"(g))
#define CP_ASYNC_COMMIT() asm volatile("cp.async.commit_group;" ::: "memory")
#define CP_ASYNC_WAIT2()  asm volatile("cp.async.wait_group 2;" ::: "memory")

#define LDTM_X32(r, addr)                                                              \
    asm volatile(                                                                      \
        "tcgen05.ld.sync.aligned.32x32b.x32.b32 "                                      \
        "{%0, %1, %2, %3, %4, %5, %6, %7, "                                            \
        " %8, %9, %10, %11, %12, %13, %14, %15, "                                      \
        " %16, %17, %18, %19, %20, %21, %22, %23, "                                    \
        " %24, %25, %26, %27, %28, %29, %30, %31}, [%32];"                             \
        : "=r"((r)[0]),  "=r"((r)[1]),  "=r"((r)[2]),  "=r"((r)[3]),                   \
          "=r"((r)[4]),  "=r"((r)[5]),  "=r"((r)[6]),  "=r"((r)[7]),                   \
          "=r"((r)[8]),  "=r"((r)[9]),  "=r"((r)[10]), "=r"((r)[11]),                  \
          "=r"((r)[12]), "=r"((r)[13]), "=r"((r)[14]), "=r"((r)[15]),                  \
          "=r"((r)[16]), "=r"((r)[17]), "=r"((r)[18]), "=r"((r)[19]),                  \
          "=r"((r)[20]), "=r"((r)[21]), "=r"((r)[22]), "=r"((r)[23]),                  \
          "=r"((r)[24]), "=r"((r)[25]), "=r"((r)[26]), "=r"((r)[27]),                  \
          "=r"((r)[28]), "=r"((r)[29]), "=r"((r)[30]), "=r"((r)[31])                   \
        : "r"(addr))

static constexpr uint64_t DESC_SW128 =
    (2ull << 61) | (1ull << 46) | (64ull << 32) | (1ull << 16);

__device__ __forceinline__ uint64_t make_desc(uint32_t addr) {
    return DESC_SW128 | ((uint64_t)(addr >> 4) & 0x3FFF);
}

__device__ __forceinline__ void mma_tf32(uint32_t d_tmem, uint64_t ad, uint64_t bd,
                                         uint32_t idesc, bool acc) {
    uint32_t en = acc ? 1u : 0u;
    asm volatile(
        "{\n\t.reg .pred p;\n\t"
        "setp.ne.u32 p, %5, 0;\n\t"
        "tcgen05.mma.cta_group::1.kind::tf32 [%0], %1, %2, %3, {%4, %4, %4, %4}, p;\n\t}"
        :: "r"(d_tmem), "l"(ad), "l"(bd), "r"(idesc), "r"(0u), "r"(en)
        : "memory");
}
#else
// ---------------------------------------------------------------------------
// Legacy mma.sync helper (plain-arch fallback pass)
// ---------------------------------------------------------------------------
__device__ __forceinline__ void mma8(float* d, const uint32_t* a, const uint32_t* b) {
    asm volatile(
        "mma.sync.aligned.m16n8k8.row.col.f32.tf32.tf32.f32 "
        "{%0,%1,%2,%3},{%4,%5,%6,%7},{%8,%9},{%0,%1,%2,%3};"
        : "+f"(d[0]), "+f"(d[1]), "+f"(d[2]), "+f"(d[3])
        : "r"(a[0]), "r"(a[1]), "r"(a[2]), "r"(a[3]), "r"(b[0]), "r"(b[1]));
}
#endif

// ---------------------------------------------------------------------------
// Unified GEMM: C[i,j] = sum_k A[i,k] * B[j,k]  (both K-major fp32)
// Grid: (N/256, M/256, Z), 256 threads, dyn smem = SMEM_TOTAL.
//   tcgen05 pass : CTA computes 256x256 via two stacked M=128,N=256 cg1 MMAs.
//   fallback pass: CTA computes 4x 128x128 tiles via mma.sync tf32.
// If A2 != null and blockIdx.z == 1, the second pointer set is used (fused
// Q/K projection launch); otherwise z indexes the batch via strides.
// ---------------------------------------------------------------------------
__global__ void __launch_bounds__(256, 1) gemm_u_kernel(
    const float* __restrict__ A, const float* __restrict__ B,
    const float* __restrict__ bias, float* __restrict__ C,
    const float* __restrict__ A2, const float* __restrict__ B2,
    const float* __restrict__ bias2, float* __restrict__ C2,
    int lda, int ldb, int ldc, int nk,
    size_t sA, size_t sB, size_t sC, int round_out)
{
    extern __shared__ char smem[];
    if (A2 != nullptr && blockIdx.z == 1) {
        A = A2; B = B2; bias = bias2; C = C2;
    } else {
        A += (size_t)blockIdx.z * sA;
        B += (size_t)blockIdx.z * sB;
        C += (size_t)blockIdx.z * sC;
    }
    const int tid  = threadIdx.x;
    const int wid  = tid >> 5;
    const int lane = tid & 31;

#if HAS_TCGEN05
    // ================== tcgen05 variant (256 x 256 per CTA) =================
    const int brow = blockIdx.y * 256;
    const int bcol = blockIdx.x * 256;
    const uint32_t sb = smem_u32(smem);

    if (tid == 0) {
        #pragma unroll
        for (int s = 0; s < NSTAGE; s++) MBARRIER_INIT(sb + SMEM_EMPTY(s), 1);
        MBARRIER_INIT(sb + SMEM_DONE, 1);
    }
    if (wid == 0) TCGEN05_ALLOC(sb + SMEM_TMEM, 512);
    __syncthreads();

    uint32_t tmem;
    asm volatile("ld.shared.b32 %0, [%1];" : "=r"(tmem) : "r"(sb + SMEM_TMEM));

    auto load_stage = [&](int s, int kit) {
        const int kbase = kit * 32;
        const uint32_t a_s = sb + SMEM_A(s);
        const uint32_t b_s = sb + SMEM_B(s);
        #pragma unroll
        for (int j = 0; j < 8; j++) {        // A: 256 rows x 8 chunks = 2048
            int c   = tid + j * 256;
            int row = c >> 3;
            int co  = (c & 7) << 4;
            const float* g = A + (size_t)(brow + row) * lda + kbase + ((c & 7) << 2);
            CP_ASYNC16(a_s + (row << 7) + (co ^ ((row & 7) << 4)), g);
        }
        #pragma unroll
        for (int j = 0; j < 8; j++) {        // B: 256 rows x 8 chunks = 2048
            int c   = tid + j * 256;
            int row = c >> 3;
            int co  = (c & 7) << 4;
            const float* g = B + (size_t)(bcol + row) * ldb + kbase + ((c & 7) << 2);
            CP_ASYNC16(b_s + (row << 7) + (co ^ ((row & 7) << 4)), g);
        }
    };

    // Prologue: stages 0..NSTAGE-2
    #pragma unroll
    for (int p = 0; p < NSTAGE - 1; p++) {
        if (p < nk) load_stage(p, p);
        CP_ASYNC_COMMIT();
    }

    for (int it = 0; it < nk; it++) {
        const int s   = it % NSTAGE;
        const int lit = it + (NSTAGE - 1);
        if (lit < nk) {
            const int ls = lit % NSTAGE;
            if (lit >= NSTAGE)
                MBARRIER_WAIT_PARITY(sb + SMEM_EMPTY(ls), (lit / NSTAGE - 1) & 1);
            load_stage(ls, lit);
        }
        CP_ASYNC_COMMIT();
        CP_ASYNC_WAIT2();                    // stage `it` resident (this thread)
        asm volatile("fence.proxy.async;" ::: "memory");
        __syncthreads();                     // all threads' stage-`it` done

        if (wid == 1 && elect_one_pred()) {
            uint64_t ad0 = make_desc(sb + SMEM_A(s));
            uint64_t ad1 = make_desc(sb + SMEM_A(s) + 16384);   // rows 128..255
            uint64_t bd  = make_desc(sb + SMEM_B(s));
            const bool first = (it == 0);
            #pragma unroll
            for (int st = 0; st < 4; st++) { // 4 x (K=8) = K-tile of 32
                const bool acc = !(first && st == 0);
                mma_tf32(tmem,       ad0 + st * 2, bd + st * 2, MMA_IDESC, acc);
                mma_tf32(tmem + 256, ad1 + st * 2, bd + st * 2, MMA_IDESC, acc);
            }
            TCGEN05_COMMIT(sb + SMEM_EMPTY(s));
        }
    }

    if (wid == 1 && elect_one_pred()) TCGEN05_COMMIT(sb + SMEM_DONE);
    MBARRIER_WAIT_PARITY(sb + SMEM_DONE, 0);
    TCGEN05_FENCE_AFTER();

    // Epilogue: warps 0-3 -> tile0 (rows brow..+127, TMEM cols 0..255),
    //           warps 4-7 -> tile1 (rows brow+128..+255, TMEM cols 256..511).
    {
        const int tile = wid >> 2;
        const int row  = brow + tile * 128 + (wid & 3) * 32 + lane;
        const uint32_t tbase = tmem + tile * 256;
        float* crow = C + (size_t)row * ldc + bcol;
        #pragma unroll 1
        for (int cb = 0; cb < 8; cb++) {
            uint32_t d[32];
            LDTM_X32(d, tbase + cb * 32);
            TCGEN05_WAIT_LD();
            #pragma unroll
            for (int j = 0; j < 32; j += 4) {
                float4 v;
                v.x = __uint_as_float(d[j + 0]);
                v.y = __uint_as_float(d[j + 1]);
                v.z = __uint_as_float(d[j + 2]);
                v.w = __uint_as_float(d[j + 3]);
                if (bias) {
                    const float4 bv = *(const float4*)&bias[bcol + cb * 32 + j];
                    v.x += bv.x; v.y += bv.y; v.z += bv.z; v.w += bv.w;
                }
                if (round_out) {
                    v.x = tf32r(v.x); v.y = tf32r(v.y);
                    v.z = tf32r(v.z); v.w = tf32r(v.w);
                }
                *(float4*)(crow + cb * 32 + j) = v;
            }
        }
    }

    TCGEN05_FENCE_BEFORE();
    __syncthreads();
    if (wid == 0) {
        TCGEN05_RELINQUISH();
        TCGEN05_DEALLOC(tmem, 512);
    }

#else
    // ===================== legacy mma.sync variant (4 x 128x128) ============
    #define BK 16
    #define AST 20
    const int wm0 = (wid >> 2) * 64;
    const int wn0 = (wid & 3) * 32;
    const int K   = nk * 32;
    const int nk2 = K / BK;

    float* As = (float*)smem;            // 2 buffers x 128*20
    float* Bs = As + 2 * 128 * AST;

    for (int mh = 0; mh < 2; mh++)
    for (int nh = 0; nh < 2; nh++) {
        const int brow = blockIdx.y * 256 + mh * 128;
        const int bcol = blockIdx.x * 256 + nh * 128;

        const int r0 = tid >> 2;
        const int c0 = (tid & 3) * 4;
        const float* Ag = A + (size_t)(brow + r0) * lda + c0;
        const float* Bg = B + (size_t)(bcol + r0) * ldb + c0;

        float4 pa0, pa1, pb0, pb1;
        {
            pa0 = *(const float4*)(Ag);
            pa1 = *(const float4*)(Ag + (size_t)64 * lda);
            pb0 = *(const float4*)(Bg);
            pb1 = *(const float4*)(Bg + (size_t)64 * ldb);
            *(float4*)&As[r0 * AST + c0]        = pa0;
            *(float4*)&As[(r0 + 64) * AST + c0] = pa1;
            *(float4*)&Bs[r0 * AST + c0]        = pb0;
            *(float4*)&Bs[(r0 + 64) * AST + c0] = pb1;
        }
        __syncthreads();

        float acc[4][4][4] = {};

        for (int kt = 0; kt < nk2; kt++) {
            const int cur = kt & 1;
            float* Ac = As + cur * 128 * AST;
            float* Bc = Bs + cur * 128 * AST;
            if (kt + 1 < nk2) {
                size_t off = (size_t)(kt + 1) * BK;
                pa0 = *(const float4*)(Ag + off);
                pa1 = *(const float4*)(Ag + off + (size_t)64 * lda);
                pb0 = *(const float4*)(Bg + off);
                pb1 = *(const float4*)(Bg + off + (size_t)64 * ldb);
            }

            #pragma unroll
            for (int ks = 0; ks < BK; ks += 8) {
                uint32_t af[4][4], bf[4][2];
                #pragma unroll
                for (int mf = 0; mf < 4; mf++) {
                    int row = wm0 + mf * 16 + (lane >> 2);
                    int col = ks + (lane & 3);
                    const float* p = &Ac[row * AST + col];
                    af[mf][0] = f2tf(p[0]);
                    af[mf][1] = f2tf(p[8 * AST]);
                    af[mf][2] = f2tf(p[4]);
                    af[mf][3] = f2tf(p[8 * AST + 4]);
                }
                #pragma unroll
                for (int nf = 0; nf < 4; nf++) {
                    int row = wn0 + nf * 8 + (lane >> 2);
                    int col = ks + (lane & 3);
                    const float* p = &Bc[row * AST + col];
                    bf[nf][0] = f2tf(p[0]);
                    bf[nf][1] = f2tf(p[4]);
                }
                #pragma unroll
                for (int mf = 0; mf < 4; mf++)
                    #pragma unroll
                    for (int nf = 0; nf < 4; nf++)
                        mma8(acc[mf][nf], af[mf], bf[nf]);
            }

            if (kt + 1 < nk2) {
                float* An = As + (1 - cur) * 128 * AST;
                float* Bn = Bs + (1 - cur) * 128 * AST;
                *(float4*)&An[r0 * AST + c0]        = pa0;
                *(float4*)&An[(r0 + 64) * AST + c0] = pa1;
                *(float4*)&Bn[r0 * AST + c0]        = pb0;
                *(float4*)&Bn[(r0 + 64) * AST + c0] = pb1;
            }
            __syncthreads();
        }

        #pragma unroll
        for (int mf = 0; mf < 4; mf++) {
            int r = brow + wm0 + mf * 16 + (lane >> 2);
            #pragma unroll
            for (int nf = 0; nf < 4; nf++) {
                int cidx = bcol + wn0 + nf * 8 + (lane & 3) * 2;
                float b0 = 0.f, b1 = 0.f;
                if (bias) { b0 = bias[cidx]; b1 = bias[cidx + 1]; }
                float o0 = acc[mf][nf][0] + b0, o1 = acc[mf][nf][1] + b1;
                float o2 = acc[mf][nf][2] + b0, o3 = acc[mf][nf][3] + b1;
                if (round_out) { o0 = tf32r(o0); o1 = tf32r(o1); o2 = tf32r(o2); o3 = tf32r(o3); }
                *(float2*)&C[(size_t)r * ldc + cidx]       = make_float2(o0, o1);
                *(float2*)&C[(size_t)(r + 8) * ldc + cidx] = make_float2(o2, o3);
            }
        }
        __syncthreads();
    }
    #undef BK
    #undef AST
#endif
}

// ---------------------------------------------------------------------------
// Prepass: tf32-round copy, two pairs in one launch (z selects pair)
// ---------------------------------------------------------------------------
__global__ void round_copy2_kernel(const float4* __restrict__ s0, float4* __restrict__ d0,
                                   const float4* __restrict__ s1, float4* __restrict__ d1,
                                   int n4)
{
    const float4* src = blockIdx.z ? s1 : s0;
    float4*       dst = blockIdx.z ? d1 : d0;
    int i = blockIdx.x * blockDim.x + threadIdx.x;
    if (i < n4) {
        float4 v = src[i];
        v.x = tf32r(v.x); v.y = tf32r(v.y); v.z = tf32r(v.z); v.w = tf32r(v.w);
        dst[i] = v;
    }
}

// ---------------------------------------------------------------------------
// Prepass: transpose + round: value [B,S,D] -> vt [B,D,S]
// ---------------------------------------------------------------------------
__global__ void transpose_round_kernel(const float* __restrict__ src,
                                       float* __restrict__ dst)
{
    __shared__ float t[32][33];
    const int b  = blockIdx.z;
    const int s0 = blockIdx.x * 32;
    const int d0 = blockIdx.y * 32;
    src += (size_t)b * SEQ * DIM;
    dst += (size_t)b * SEQ * DIM;
    const int tx = threadIdx.x, ty = threadIdx.y;
    #pragma unroll
    for (int j = 0; j < 32; j += 8)
        t[ty + j][tx] = src[(size_t)(s0 + ty + j) * DIM + d0 + tx];
    __syncthreads();
    #pragma unroll
    for (int j = 0; j < 32; j += 8)
        dst[(size_t)(d0 + ty + j) * SEQ + s0 + tx] = tf32r(t[tx][ty + j]);
}

// ---------------------------------------------------------------------------
// Row softmax over 2048 cols, scale folded in, output tf32-rounded, in place.
// ---------------------------------------------------------------------------
__global__ void softmax_kernel(float* __restrict__ x)
{
    const int row = blockIdx.x;
    float* p = x + (size_t)row * SEQ;
    const int tid = threadIdx.x;

    float v[8];
    float m = -1e30f;
    #pragma unroll
    for (int i = 0; i < 8; i++) {
        v[i] = p[tid + i * 256];
        m = fmaxf(m, v[i]);
    }

    __shared__ float red[8];
    #pragma unroll
    for (int o = 16; o; o >>= 1) m = fmaxf(m, __shfl_xor_sync(0xffffffffu, m, o));
    if ((tid & 31) == 0) red[tid >> 5] = m;
    __syncthreads();
    m = red[0];
    #pragma unroll
    for (int i = 1; i < 8; i++) m = fmaxf(m, red[i]);
    __syncthreads();

    float s = 0.f;
    #pragma unroll
    for (int i = 0; i < 8; i++) {
        v[i] = __expf((v[i] - m) * SOFTMAX_SCALE);
        s += v[i];
    }
    #pragma unroll
    for (int o = 16; o; o >>= 1) s += __shfl_xor_sync(0xffffffffu, s, o);
    if ((tid & 31) == 0) red[tid >> 5] = s;
    __syncthreads();
    s = red[0];
    #pragma unroll
    for (int i = 1; i < 8; i++) s += red[i];
    const float inv = 1.0f / s;

    #pragma unroll
    for (int i = 0; i < 8; i++) p[tid + i * 256] = tf32r(v[i] * inv);
}

// ---------------------------------------------------------------------------
extern "C" void kernel_launch(void* const* d_in, const int* in_sizes, int n_in,
                              void* d_out, int out_size)
{
    const float* query  = (const float*)d_in[0];
    const float* key_in = (const float*)d_in[1];
    const float* value  = (const float*)d_in[2];
    const float* Wq     = (const float*)d_in[3];
    const float* bq     = (const float*)d_in[4];
    const float* Wk     = (const float*)d_in[5];
    const float* bk     = (const float*)d_in[6];
    // Wv/bv (d_in[7], d_in[8]) are intentionally unused (reference quirk).
    float* out = (float*)d_out;

    float *qr, *kr, *wq, *wk, *vt, *q, *k, *dots;
    cudaGetSymbolAddress((void**)&qr, g_qr);
    cudaGetSymbolAddress((void**)&kr, g_kr);
    cudaGetSymbolAddress((void**)&wq, g_wq);
    cudaGetSymbolAddress((void**)&wk, g_wk);
    cudaGetSymbolAddress((void**)&vt, g_vt);
    cudaGetSymbolAddress((void**)&q,  g_q);
    cudaGetSymbolAddress((void**)&k,  g_k);
    cudaGetSymbolAddress((void**)&dots, g_dots);

    cudaFuncSetAttribute(gemm_u_kernel,
                         cudaFuncAttributeMaxDynamicSharedMemorySize, SMEM_TOTAL);

    // Prepass: tf32-round all raw MMA operands
    const int nBig = BATCH * SEQ * DIM / 4;
    const int nW   = DIM * DIM / 4;
    round_copy2_kernel<<<dim3((nBig + 255) / 256, 1, 2), 256>>>(
        (const float4*)query, (float4*)qr, (const float4*)key_in, (float4*)kr, nBig);
    round_copy2_kernel<<<dim3((nW + 255) / 256, 1, 2), 256>>>(
        (const float4*)Wq, (float4*)wq, (const float4*)Wk, (float4*)wk, nW);
    transpose_round_kernel<<<dim3(SEQ / 32, DIM / 32, BATCH), dim3(32, 8)>>>(value, vt);

    // 1+2) fused projections: z=0 -> q = query@Wq^T+bq, z=1 -> k = key@Wk^T+bk
    gemm_u_kernel<<<dim3(DIM / 256, (BATCH * SEQ) / 256, 2), 256, SMEM_TOTAL>>>(
        qr, wq, bq, q, kr, wk, bk, k, DIM, DIM, DIM, DIM / 32, 0, 0, 0, 1);

    // 3) dots[b] = q[b] @ k[b]^T  (M=N=2048, K=1024)
    gemm_u_kernel<<<dim3(SEQ / 256, SEQ / 256, BATCH), 256, SMEM_TOTAL>>>(
        q, k, nullptr, dots, nullptr, nullptr, nullptr, nullptr,
        DIM, DIM, SEQ, DIM / 32,
        (size_t)SEQ * DIM, (size_t)SEQ * DIM, (size_t)SEQ * SEQ, 0);

    // 4) softmax rows (scale folded in, output rounded)
    softmax_kernel<<<BATCH * SEQ, 256>>>(dots);

    // 5) out[b] = attn[b] @ vt[b]^T  (M=2048, N=1024, K=2048)
    gemm_u_kernel<<<dim3(DIM / 256, SEQ / 256, BATCH), 256, SMEM_TOTAL>>>(
        dots, vt, nullptr, out, nullptr, nullptr, nullptr, nullptr,
        SEQ, SEQ, DIM, SEQ / 32,
        (size_t)SEQ * SEQ, (size_t)SEQ * DIM, (size_t)SEQ * DIM, 0);
}

// round 7
// speedup vs baseline: 1.9577x; 1.9577x over previous
#include <cuda_runtime.h>
#include <cuda_bf16.h>
#include <cstdint>
#include <cstddef>

// Problem constants
#define BATCH 4
#define SEQ   2048
#define DIM   1024
#define SOFTMAX_SCALE 0.03125f  // 1/sqrt(1024)

// ---------------------------------------------------------------------------
// tcgen05 availability: only in arch-specific ('a' / family) compile passes.
// Plain compute_103 pass falls back to legacy mma.sync.
// ---------------------------------------------------------------------------
#if defined(__CUDA_ARCH__) && (__CUDA_ARCH__ >= 1000) && \
    (defined(__CUDA_ARCH_FEAT_SM103_ALL) || defined(__CUDA_ARCH_FEAT_SM100_ALL) || \
     defined(__CUDA_ARCH_FEAT_SM101_ALL) || defined(__CUDA_ARCH_FAMILY_SPECIFIC__))
#define HAS_TCGEN05 1
#else
#define HAS_TCGEN05 0
#endif

// CTA tile: 256 (M) x 256 (N) as two stacked M=128,N=256 cg1 MMAs sharing one B tile.
#define NSTAGE 3
#define NTHREADS 288      // 256 producer threads + 1 MMA warp

// SMEM layout (bytes, within dynamic smem)
#define SMEM_TMEM   0
#define SMEM_EMPTY(s) (16 + 8 * (s))     // released by tcgen05.commit
#define SMEM_FULL(s)  (40 + 8 * (s))     // 256 cp.async arrivals
#define SMEM_DONE   64
#define SMEM_A(s)   (1024 + (s) * 32768)                   // 256 rows x 128B
#define SMEM_B(s)   (1024 + NSTAGE * 32768 + (s) * 32768)  // 256 rows x 128B
#define SMEM_TOTAL  (1024 + 2 * NSTAGE * 32768)            // 197632

// idesc: kind::tf32, D=f32, A=B=tf32 (enc 2), K-major, M=128, N=256
#define MMA_IDESC ((1u << 4) | (2u << 7) | (2u << 10) | (32u << 17) | (8u << 24))

// ---------------------------------------------------------------------------
// Scratch (device globals; allocation in kernel_launch is forbidden)
// ---------------------------------------------------------------------------
__device__ float g_qr[BATCH * SEQ * DIM];   // query, tf32-rounded
__device__ float g_kr[BATCH * SEQ * DIM];   // key_in, tf32-rounded
__device__ float g_wq[DIM * DIM];           // Wq, tf32-rounded
__device__ float g_wk[DIM * DIM];           // Wk, tf32-rounded
__device__ float g_vt[BATCH * SEQ * DIM];   // value transposed [B][D][S], rounded
__device__ float g_q [BATCH * SEQ * DIM];   // projected q
__device__ float g_k [BATCH * SEQ * DIM];   // projected k
__device__ float g_dots[(size_t)BATCH * SEQ * SEQ];

// ---------------------------------------------------------------------------
// Common helpers
// ---------------------------------------------------------------------------
__device__ __forceinline__ float tf32r(float f) {
    uint32_t u;
    asm("cvt.rna.tf32.f32 %0, %1;" : "=r"(u) : "f"(f));
    return __uint_as_float(u);
}

__device__ __forceinline__ uint32_t f2tf(float f) {
    uint32_t u;
    asm("cvt.rna.tf32.f32 %0, %1;" : "=r"(u) : "f"(f));
    return u;
}

__device__ __forceinline__ uint32_t smem_u32(const void* p) {
    uint32_t a;
    asm("{ .reg .u64 t; cvta.to.shared.u64 t, %1; cvt.u32.u64 %0, t; }" : "=r"(a) : "l"(p));
    return a;
}

#if HAS_TCGEN05
// ---------------------------------------------------------------------------
// tcgen05-only helpers (arch-specific pass)
// ---------------------------------------------------------------------------
__device__ __forceinline__ uint32_t elect_one_pred() {
    uint32_t pred;
    asm volatile(
        "{\n\t.reg .pred p;\n\t"
        "elect.sync _|p, 0xFFFFFFFF;\n\t"
        "selp.b32 %0, 1, 0, p;\n\t}"
        : "=r"(pred));
    return pred;
}

#define MBARRIER_INIT(addr, cnt) \
    asm volatile("mbarrier.init.shared.b64 [%0], %1;" :: "r"((uint32_t)(addr)), "r"((uint32_t)(cnt)) : "memory")

#define MBARRIER_WAIT_PARITY(addr, parity) do {                                        \
    uint32_t _mbar = (uint32_t)(addr);                                                 \
    uint32_t _par  = (uint32_t)(parity);                                               \
    uint32_t _done;                                                                    \
    asm volatile(                                                                      \
        "{\n\t.reg .pred p;\n\t"                                                       \
        "mbarrier.try_wait.parity.acquire.cta.shared::cta.b64 p, [%1], %2;\n\t"        \
        "selp.b32 %0, 1, 0, p;\n\t}"                                                   \
        : "=r"(_done) : "r"(_mbar), "r"(_par) : "memory");                             \
    if (!_done) {                                                                      \
        asm volatile(                                                                  \
            "{\n\t.reg .pred P1;\n\t"                                                  \
            "WAIT_LOOP_%=:\n\t"                                                        \
            "mbarrier.try_wait.parity.acquire.cta.shared::cta.b64 P1, [%0], %1, 0x989680;\n\t" \
            "@P1 bra.uni WAIT_DONE_%=;\n\t"                                            \
            "bra.uni WAIT_LOOP_%=;\n\t"                                                 \
            "WAIT_DONE_%=:\n\t}"                                                        \
            :: "r"(_mbar), "r"(_par) : "memory");                                      \
    }                                                                                  \
} while (0)

#define TCGEN05_ALLOC(smem_addr, ncols) \
    asm volatile("tcgen05.alloc.cta_group::1.sync.aligned.shared::cta.b32 [%0], %1;" \
        :: "r"((uint32_t)(smem_addr)), "r"((uint32_t)(ncols)) : "memory")
#define TCGEN05_DEALLOC(tmem, ncols) \
    asm volatile("tcgen05.dealloc.cta_group::1.sync.aligned.b32 %0, %1;" :: "r"(tmem), "r"((uint32_t)(ncols)))
#define TCGEN05_RELINQUISH() \
    asm volatile("tcgen05.relinquish_alloc_permit.cta_group::1.sync.aligned;")
#define TCGEN05_COMMIT(mbar) \
    asm volatile("tcgen05.commit.cta_group::1.mbarrier::arrive::one.shared::cluster.b64 [%0];" \
        :: "r"((uint32_t)(mbar)) : "memory")
#define TCGEN05_FENCE_AFTER()  asm volatile("tcgen05.fence::after_thread_sync;"  ::: "memory")
#define TCGEN05_FENCE_BEFORE() asm volatile("tcgen05.fence::before_thread_sync;" ::: "memory")
#define TCGEN05_WAIT_LD()      asm volatile("tcgen05.wait::ld.sync.aligned;"     ::: "memory")

#define CP_ASYNC16(sm, g) \
    asm volatile("cp.async.cg.shared.global [%0], [%1], 16;" :: "r"(sm), "l"(g))
// Arrive on mbarrier when ALL of this thread's prior cp.asyncs have completed.
#define CP_ASYNC_MBAR_ARRIVE(addr) \
    asm volatile("cp.async.mbarrier.arrive.noinc.shared::cta.b64 [%0];" \
        :: "r"((uint32_t)(addr)) : "memory")

#define FENCE_PROXY_ASYNC() \
    asm volatile("fence.proxy.async.shared::cta;" ::: "memory")

#define LDTM_X32(r, addr)                                                              \
    asm volatile(                                                                      \
        "tcgen05.ld.sync.aligned.32x32b.x32.b32 "                                      \
        "{%0, %1, %2, %3, %4, %5, %6, %7, "                                            \
        " %8, %9, %10, %11, %12, %13, %14, %15, "                                      \
        " %16, %17, %18, %19, %20, %21, %22, %23, "                                    \
        " %24, %25, %26, %27, %28, %29, %30, %31}, [%32];"                             \
        : "=r"((r)[0]),  "=r"((r)[1]),  "=r"((r)[2]),  "=r"((r)[3]),                   \
          "=r"((r)[4]),  "=r"((r)[5]),  "=r"((r)[6]),  "=r"((r)[7]),                   \
          "=r"((r)[8]),  "=r"((r)[9]),  "=r"((r)[10]), "=r"((r)[11]),                  \
          "=r"((r)[12]), "=r"((r)[13]), "=r"((r)[14]), "=r"((r)[15]),                  \
          "=r"((r)[16]), "=r"((r)[17]), "=r"((r)[18]), "=r"((r)[19]),                  \
          "=r"((r)[20]), "=r"((r)[21]), "=r"((r)[22]), "=r"((r)[23]),                  \
          "=r"((r)[24]), "=r"((r)[25]), "=r"((r)[26]), "=r"((r)[27]),                  \
          "=r"((r)[28]), "=r"((r)[29]), "=r"((r)[30]), "=r"((r)[31])                   \
        : "r"(addr))

static constexpr uint64_t DESC_SW128 =
    (2ull << 61) | (1ull << 46) | (64ull << 32) | (1ull << 16);

__device__ __forceinline__ uint64_t make_desc(uint32_t addr) {
    return DESC_SW128 | ((uint64_t)(addr >> 4) & 0x3FFF);
}

__device__ __forceinline__ void mma_tf32(uint32_t d_tmem, uint64_t ad, uint64_t bd,
                                         uint32_t idesc, bool acc) {
    uint32_t en = acc ? 1u : 0u;
    asm volatile(
        "{\n\t.reg .pred p;\n\t"
        "setp.ne.u32 p, %5, 0;\n\t"
        "tcgen05.mma.cta_group::1.kind::tf32 [%0], %1, %2, %3, {%4, %4, %4, %4}, p;\n\t}"
        :: "r"(d_tmem), "l"(ad), "l"(bd), "r"(idesc), "r"(0u), "r"(en)
        : "memory");
}
#else
// ---------------------------------------------------------------------------
// Legacy mma.sync helper (plain-arch fallback pass)
// ---------------------------------------------------------------------------
__device__ __forceinline__ void mma8(float* d, const uint32_t* a, const uint32_t* b) {
    asm volatile(
        "mma.sync.aligned.m16n8k8.row.col.f32.tf32.tf32.f32 "
        "{%0,%1,%2,%3},{%4,%5,%6,%7},{%8,%9},{%0,%1,%2,%3};"
        : "+f"(d[0]), "+f"(d[1]), "+f"(d[2]), "+f"(d[3])
        : "r"(a[0]), "r"(a[1]), "r"(a[2]), "r"(a[3]), "r"(b[0]), "r"(b[1]));
}
#endif

// ---------------------------------------------------------------------------
// Unified GEMM: C[i,j] = sum_k A[i,k] * B[j,k]  (both K-major fp32)
// Grid: (N/256, M/256, Z), NTHREADS threads, dyn smem = SMEM_TOTAL.
//   tcgen05 pass : warp-specialized producer/consumer pipeline.
//     threads 0..255 : cp.async producers, run ahead NSTAGE deep,
//                      throttled only by empty(s); signal full(s) via
//                      cp.async.mbarrier.arrive.
//     warp 8         : MMA issuer (wait full -> 8 dispatches -> commit empty).
//   fallback pass: CTA computes 4x 128x128 tiles via mma.sync tf32.
// If A2 != null and blockIdx.z == 1, the second pointer set is used (fused
// Q/K projection launch); otherwise z indexes the batch via strides.
// ---------------------------------------------------------------------------
__global__ void __launch_bounds__(NTHREADS, 1) gemm_u_kernel(
    const float* __restrict__ A, const float* __restrict__ B,
    const float* __restrict__ bias, float* __restrict__ C,
    const float* __restrict__ A2, const float* __restrict__ B2,
    const float* __restrict__ bias2, float* __restrict__ C2,
    int lda, int ldb, int ldc, int nk,
    size_t sA, size_t sB, size_t sC, int round_out)
{
    extern __shared__ char smem[];
    if (A2 != nullptr && blockIdx.z == 1) {
        A = A2; B = B2; bias = bias2; C = C2;
    } else {
        A += (size_t)blockIdx.z * sA;
        B += (size_t)blockIdx.z * sB;
        C += (size_t)blockIdx.z * sC;
    }
    const int tid  = threadIdx.x;
    const int wid  = tid >> 5;
    const int lane = tid & 31;

#if HAS_TCGEN05
    // ================== tcgen05 variant (256 x 256 per CTA) =================
    const int brow = blockIdx.y * 256;
    const int bcol = blockIdx.x * 256;
    const uint32_t sb = smem_u32(smem);

    if (tid == 0) {
        #pragma unroll
        for (int s = 0; s < NSTAGE; s++) {
            MBARRIER_INIT(sb + SMEM_EMPTY(s), 1);    // tcgen05.commit arrives once
            MBARRIER_INIT(sb + SMEM_FULL(s), 256);   // one arrive per producer thread
        }
        MBARRIER_INIT(sb + SMEM_DONE, 1);
    }
    if (wid == 0) TCGEN05_ALLOC(sb + SMEM_TMEM, 512);
    __syncthreads();

    uint32_t tmem;
    asm volatile("ld.shared.b32 %0, [%1];" : "=r"(tmem) : "r"(sb + SMEM_TMEM));

    if (tid < 256) {
        // ---------------- producer role: run ahead, throttled by empty(s) ----
        #pragma unroll 1
        for (int l = 0; l < nk; l++) {
            const int s = l % NSTAGE;
            if (l >= NSTAGE)
                MBARRIER_WAIT_PARITY(sb + SMEM_EMPTY(s), (l / NSTAGE - 1) & 1);
            const int kbase = l * 32;
            const uint32_t a_s = sb + SMEM_A(s);
            const uint32_t b_s = sb + SMEM_B(s);
            #pragma unroll
            for (int j = 0; j < 8; j++) {        // A: 256 rows x 8 chunks
                int c   = tid + j * 256;
                int row = c >> 3;
                int co  = (c & 7) << 4;
                const float* g = A + (size_t)(brow + row) * lda + kbase + ((c & 7) << 2);
                CP_ASYNC16(a_s + (row << 7) + (co ^ ((row & 7) << 4)), g);
            }
            #pragma unroll
            for (int j = 0; j < 8; j++) {        // B: 256 rows x 8 chunks
                int c   = tid + j * 256;
                int row = c >> 3;
                int co  = (c & 7) << 4;
                const float* g = B + (size_t)(bcol + row) * ldb + kbase + ((c & 7) << 2);
                CP_ASYNC16(b_s + (row << 7) + (co ^ ((row & 7) << 4)), g);
            }
            CP_ASYNC_MBAR_ARRIVE(sb + SMEM_FULL(s));
        }
    } else if (wid == 8) {
        // ---------------- MMA issuer role ------------------------------------
        if (elect_one_pred()) {
            #pragma unroll 1
            for (int it = 0; it < nk; it++) {
                const int s = it % NSTAGE;
                MBARRIER_WAIT_PARITY(sb + SMEM_FULL(s), (it / NSTAGE) & 1);
                FENCE_PROXY_ASYNC();
                uint64_t ad0 = make_desc(sb + SMEM_A(s));
                uint64_t ad1 = make_desc(sb + SMEM_A(s) + 16384);   // rows 128..255
                uint64_t bd  = make_desc(sb + SMEM_B(s));
                const bool first = (it == 0);
                #pragma unroll
                for (int st = 0; st < 4; st++) {  // 4 x (K=8) = K-tile of 32
                    const bool acc = !(first && st == 0);
                    mma_tf32(tmem,       ad0 + st * 2, bd + st * 2, MMA_IDESC, acc);
                    mma_tf32(tmem + 256, ad1 + st * 2, bd + st * 2, MMA_IDESC, acc);
                }
                TCGEN05_COMMIT(sb + SMEM_EMPTY(s));
            }
            TCGEN05_COMMIT(sb + SMEM_DONE);
        }
    }

    // All threads rendezvous on final MMA completion.
    MBARRIER_WAIT_PARITY(sb + SMEM_DONE, 0);
    TCGEN05_FENCE_AFTER();

    // Epilogue: warps 0-3 -> tile0 (rows brow..+127, TMEM cols 0..255),
    //           warps 4-7 -> tile1 (rows brow+128..+255, TMEM cols 256..511).
    if (wid < 8) {
        const int tile = wid >> 2;
        const int row  = brow + tile * 128 + (wid & 3) * 32 + lane;
        const uint32_t tbase = tmem + tile * 256;
        float* crow = C + (size_t)row * ldc + bcol;
        #pragma unroll 1
        for (int cb = 0; cb < 8; cb++) {
            uint32_t d[32];
            LDTM_X32(d, tbase + cb * 32);
            TCGEN05_WAIT_LD();
            #pragma unroll
            for (int j = 0; j < 32; j += 4) {
                float4 v;
                v.x = __uint_as_float(d[j + 0]);
                v.y = __uint_as_float(d[j + 1]);
                v.z = __uint_as_float(d[j + 2]);
                v.w = __uint_as_float(d[j + 3]);
                if (bias) {
                    const float4 bv = *(const float4*)&bias[bcol + cb * 32 + j];
                    v.x += bv.x; v.y += bv.y; v.z += bv.z; v.w += bv.w;
                }
                if (round_out) {
                    v.x = tf32r(v.x); v.y = tf32r(v.y);
                    v.z = tf32r(v.z); v.w = tf32r(v.w);
                }
                *(float4*)(crow + cb * 32 + j) = v;
            }
        }
    }

    TCGEN05_FENCE_BEFORE();
    __syncthreads();
    if (wid == 0) {
        TCGEN05_RELINQUISH();
        TCGEN05_DEALLOC(tmem, 512);
    }

#else
    // ===================== legacy mma.sync variant (4 x 128x128) ============
    #define BK 16
    #define AST 20
    if (tid < 256) {
    const int wm0 = (wid >> 2) * 64;
    const int wn0 = (wid & 3) * 32;
    const int K   = nk * 32;
    const int nk2 = K / BK;

    float* As = (float*)smem;            // 2 buffers x 128*20
    float* Bs = As + 2 * 128 * AST;

    for (int mh = 0; mh < 2; mh++)
    for (int nh = 0; nh < 2; nh++) {
        const int brow = blockIdx.y * 256 + mh * 128;
        const int bcol = blockIdx.x * 256 + nh * 128;

        const int r0 = tid >> 2;
        const int c0 = (tid & 3) * 4;
        const float* Ag = A + (size_t)(brow + r0) * lda + c0;
        const float* Bg = B + (size_t)(bcol + r0) * ldb + c0;

        float4 pa0, pa1, pb0, pb1;
        {
            pa0 = *(const float4*)(Ag);
            pa1 = *(const float4*)(Ag + (size_t)64 * lda);
            pb0 = *(const float4*)(Bg);
            pb1 = *(const float4*)(Bg + (size_t)64 * ldb);
            *(float4*)&As[r0 * AST + c0]        = pa0;
            *(float4*)&As[(r0 + 64) * AST + c0] = pa1;
            *(float4*)&Bs[r0 * AST + c0]        = pb0;
            *(float4*)&Bs[(r0 + 64) * AST + c0] = pb1;
        }
        __syncthreads();

        float acc[4][4][4] = {};

        for (int kt = 0; kt < nk2; kt++) {
            const int cur = kt & 1;
            float* Ac = As + cur * 128 * AST;
            float* Bc = Bs + cur * 128 * AST;
            if (kt + 1 < nk2) {
                size_t off = (size_t)(kt + 1) * BK;
                pa0 = *(const float4*)(Ag + off);
                pa1 = *(const float4*)(Ag + off + (size_t)64 * lda);
                pb0 = *(const float4*)(Bg + off);
                pb1 = *(const float4*)(Bg + off + (size_t)64 * ldb);
            }

            #pragma unroll
            for (int ks = 0; ks < BK; ks += 8) {
                uint32_t af[4][4], bf[4][2];
                #pragma unroll
                for (int mf = 0; mf < 4; mf++) {
                    int row = wm0 + mf * 16 + (lane >> 2);
                    int col = ks + (lane & 3);
                    const float* p = &Ac[row * AST + col];
                    af[mf][0] = f2tf(p[0]);
                    af[mf][1] = f2tf(p[8 * AST]);
                    af[mf][2] = f2tf(p[4]);
                    af[mf][3] = f2tf(p[8 * AST + 4]);
                }
                #pragma unroll
                for (int nf = 0; nf < 4; nf++) {
                    int row = wn0 + nf * 8 + (lane >> 2);
                    int col = ks + (lane & 3);
                    const float* p = &Bc[row * AST + col];
                    bf[nf][0] = f2tf(p[0]);
                    bf[nf][1] = f2tf(p[4]);
                }
                #pragma unroll
                for (int mf = 0; mf < 4; mf++)
                    #pragma unroll
                    for (int nf = 0; nf < 4; nf++)
                        mma8(acc[mf][nf], af[mf], bf[nf]);
            }

            if (kt + 1 < nk2) {
                float* An = As + (1 - cur) * 128 * AST;
                float* Bn = Bs + (1 - cur) * 128 * AST;
                *(float4*)&An[r0 * AST + c0]        = pa0;
                *(float4*)&An[(r0 + 64) * AST + c0] = pa1;
                *(float4*)&Bn[r0 * AST + c0]        = pb0;
                *(float4*)&Bn[(r0 + 64) * AST + c0] = pb1;
            }
            __syncthreads();
        }

        #pragma unroll
        for (int mf = 0; mf < 4; mf++) {
            int r = brow + wm0 + mf * 16 + (lane >> 2);
            #pragma unroll
            for (int nf = 0; nf < 4; nf++) {
                int cidx = bcol + wn0 + nf * 8 + (lane & 3) * 2;
                float b0 = 0.f, b1 = 0.f;
                if (bias) { b0 = bias[cidx]; b1 = bias[cidx + 1]; }
                float o0 = acc[mf][nf][0] + b0, o1 = acc[mf][nf][1] + b1;
                float o2 = acc[mf][nf][2] + b0, o3 = acc[mf][nf][3] + b1;
                if (round_out) { o0 = tf32r(o0); o1 = tf32r(o1); o2 = tf32r(o2); o3 = tf32r(o3); }
                *(float2*)&C[(size_t)r * ldc + cidx]       = make_float2(o0, o1);
                *(float2*)&C[(size_t)(r + 8) * ldc + cidx] = make_float2(o2, o3);
            }
        }
        __syncthreads();
    }
    }
    #undef BK
    #undef AST
#endif
}

// ---------------------------------------------------------------------------
// Prepass: tf32-round copy, two pairs in one launch (z selects pair)
// ---------------------------------------------------------------------------
__global__ void round_copy2_kernel(const float4* __restrict__ s0, float4* __restrict__ d0,
                                   const float4* __restrict__ s1, float4* __restrict__ d1,
                                   int n4)
{
    const float4* src = blockIdx.z ? s1 : s0;
    float4*       dst = blockIdx.z ? d1 : d0;
    int i = blockIdx.x * blockDim.x + threadIdx.x;
    if (i < n4) {
        float4 v = src[i];
        v.x = tf32r(v.x); v.y = tf32r(v.y); v.z = tf32r(v.z); v.w = tf32r(v.w);
        dst[i] = v;
    }
}

// ---------------------------------------------------------------------------
// Prepass: transpose + round: value [B,S,D] -> vt [B,D,S]
// ---------------------------------------------------------------------------
__global__ void transpose_round_kernel(const float* __restrict__ src,
                                       float* __restrict__ dst)
{
    __shared__ float t[32][33];
    const int b  = blockIdx.z;
    const int s0 = blockIdx.x * 32;
    const int d0 = blockIdx.y * 32;
    src += (size_t)b * SEQ * DIM;
    dst += (size_t)b * SEQ * DIM;
    const int tx = threadIdx.x, ty = threadIdx.y;
    #pragma unroll
    for (int j = 0; j < 32; j += 8)
        t[ty + j][tx] = src[(size_t)(s0 + ty + j) * DIM + d0 + tx];
    __syncthreads();
    #pragma unroll
    for (int j = 0; j < 32; j += 8)
        dst[(size_t)(d0 + ty + j) * SEQ + s0 + tx] = tf32r(t[tx][ty + j]);
}

// ---------------------------------------------------------------------------
// Row softmax over 2048 cols, scale folded in, output tf32-rounded, in place.
// ---------------------------------------------------------------------------
__global__ void softmax_kernel(float* __restrict__ x)
{
    const int row = blockIdx.x;
    float* p = x + (size_t)row * SEQ;
    const int tid = threadIdx.x;

    float v[8];
    float m = -1e30f;
    #pragma unroll
    for (int i = 0; i < 8; i++) {
        v[i] = p[tid + i * 256];
        m = fmaxf(m, v[i]);
    }

    __shared__ float red[8];
    #pragma unroll
    for (int o = 16; o; o >>= 1) m = fmaxf(m, __shfl_xor_sync(0xffffffffu, m, o));
    if ((tid & 31) == 0) red[tid >> 5] = m;
    __syncthreads();
    m = red[0];
    #pragma unroll
    for (int i = 1; i < 8; i++) m = fmaxf(m, red[i]);
    __syncthreads();

    float s = 0.f;
    #pragma unroll
    for (int i = 0; i < 8; i++) {
        v[i] = __expf((v[i] - m) * SOFTMAX_SCALE);
        s += v[i];
    }
    #pragma unroll
    for (int o = 16; o; o >>= 1) s += __shfl_xor_sync(0xffffffffu, s, o);
    if ((tid & 31) == 0) red[tid >> 5] = s;
    __syncthreads();
    s = red[0];
    #pragma unroll
    for (int i = 1; i < 8; i++) s += red[i];
    const float inv = 1.0f / s;

    #pragma unroll
    for (int i = 0; i < 8; i++) p[tid + i * 256] = tf32r(v[i] * inv);
}

// ---------------------------------------------------------------------------
extern "C" void kernel_launch(void* const* d_in, const int* in_sizes, int n_in,
                              void* d_out, int out_size)
{
    const float* query  = (const float*)d_in[0];
    const float* key_in = (const float*)d_in[1];
    const float* value  = (const float*)d_in[2];
    const float* Wq     = (const float*)d_in[3];
    const float* bq     = (const float*)d_in[4];
    const float* Wk     = (const float*)d_in[5];
    const float* bk     = (const float*)d_in[6];
    // Wv/bv (d_in[7], d_in[8]) are intentionally unused (reference quirk).
    float* out = (float*)d_out;

    float *qr, *kr, *wq, *wk, *vt, *q, *k, *dots;
    cudaGetSymbolAddress((void**)&qr, g_qr);
    cudaGetSymbolAddress((void**)&kr, g_kr);
    cudaGetSymbolAddress((void**)&wq, g_wq);
    cudaGetSymbolAddress((void**)&wk, g_wk);
    cudaGetSymbolAddress((void**)&vt, g_vt);
    cudaGetSymbolAddress((void**)&q,  g_q);
    cudaGetSymbolAddress((void**)&k,  g_k);
    cudaGetSymbolAddress((void**)&dots, g_dots);

    cudaFuncSetAttribute(gemm_u_kernel,
                         cudaFuncAttributeMaxDynamicSharedMemorySize, SMEM_TOTAL);

    // Prepass: tf32-round all raw MMA operands
    const int nBig = BATCH * SEQ * DIM / 4;
    const int nW   = DIM * DIM / 4;
    round_copy2_kernel<<<dim3((nBig + 255) / 256, 1, 2), 256>>>(
        (const float4*)query, (float4*)qr, (const float4*)key_in, (float4*)kr, nBig);
    round_copy2_kernel<<<dim3((nW + 255) / 256, 1, 2), 256>>>(
        (const float4*)Wq, (float4*)wq, (const float4*)Wk, (float4*)wk, nW);
    transpose_round_kernel<<<dim3(SEQ / 32, DIM / 32, BATCH), dim3(32, 8)>>>(value, vt);

    // 1+2) fused projections: z=0 -> q = query@Wq^T+bq, z=1 -> k = key@Wk^T+bk
    gemm_u_kernel<<<dim3(DIM / 256, (BATCH * SEQ) / 256, 2), NTHREADS, SMEM_TOTAL>>>(
        qr, wq, bq, q, kr, wk, bk, k, DIM, DIM, DIM, DIM / 32, 0, 0, 0, 1);

    // 3) dots[b] = q[b] @ k[b]^T  (M=N=2048, K=1024)
    gemm_u_kernel<<<dim3(SEQ / 256, SEQ / 256, BATCH), NTHREADS, SMEM_TOTAL>>>(
        q, k, nullptr, dots, nullptr, nullptr, nullptr, nullptr,
        DIM, DIM, SEQ, DIM / 32,
        (size_t)SEQ * DIM, (size_t)SEQ * DIM, (size_t)SEQ * SEQ, 0);

    // 4) softmax rows (scale folded in, output rounded)
    softmax_kernel<<<BATCH * SEQ, 256>>>(dots);

    // 5) out[b] = attn[b] @ vt[b]^T  (M=2048, N=1024, K=2048)
    gemm_u_kernel<<<dim3(DIM / 256, SEQ / 256, BATCH), NTHREADS, SMEM_TOTAL>>>(
        dots, vt, nullptr, out, nullptr, nullptr, nullptr, nullptr,
        SEQ, SEQ, DIM, SEQ / 32,
        (size_t)SEQ * SEQ, (size_t)SEQ * DIM, (size_t)SEQ * DIM, 0);
}